// round 3
// baseline (speedup 1.0000x reference)
#include <cuda_runtime.h>
#include <cstdint>
#include <cstddef>

#define BS 4
#define C 64
#define H 64
#define W 64
#define HS 256
#define WSZ 256
#define E 4
#define KD 8
#define PAD 8
#define PW 80
#define PPLANE (PW*PW)
#define NP 16

// ---------------- device globals (static scratch; no allocation) ----------------
__device__ float g_xpad[BS*C*PPLANE];     // zero-padded input, [b][c][80][80]
__device__ float g_mean[C];
__device__ float g_emb[C][4][NP];         // emb[c][f][p]
__device__ float g_M1[NP][C][KD];         // per-phase compress  mid[k] += M1[p][c][k]*fea
__device__ float g_M2[NP][C][KD];         // per-phase expand    out[c] += M2[p][c][k]*mid[k]
__device__ float4 g_tabW[NP][C];          // bilinear weights (w00,w01,w10,w11)
__device__ int    g_tabJ[NP][C];          // byte offset into padded plane
__device__ float  g_off[C][NP][2];        // raw offsets (fallback path)
__device__ int    g_ok;

__device__ __forceinline__ float sigmoidf_(float v) { return 1.f / (1.f + expf(-v)); }

__device__ __forceinline__ void fma2(unsigned long long &d, unsigned long long a, unsigned long long b) {
    asm("fma.rn.f32x2 %0, %1, %2, %0;" : "+l"(d) : "l"(a), "l"(b));
}

// ---------------- K0: zero-pad x into g_xpad, reset flag ----------------
__global__ void k_pad(const float* __restrict__ x) {
    int i = blockIdx.x * 256 + threadIdx.x;
    if (i == 0) g_ok = 1;
    if (i >= BS*C*PPLANE) return;
    int xx = i % PW;
    int rest = i / PW;
    int yy = rest % PW;
    int bc = rest / PW;
    float v = 0.f;
    if (yy >= PAD && yy < PAD + H && xx >= PAD && xx < PAD + W)
        v = x[(size_t)bc * (H*W) + (yy - PAD) * W + (xx - PAD)];
    g_xpad[i] = v;
}

// ---------------- K1: per-channel mean of x over (b,h,w) ----------------
__global__ void k_mean(const float* __restrict__ x) {
    int c = blockIdx.x;
    int t = threadIdx.x;
    float s = 0.f;
    for (int b = 0; b < BS; b++) {
        const float* pl = x + (size_t)(b*C + c) * (H*W);
        for (int i = t; i < H*W; i += 256) s += pl[i];
    }
    __shared__ float red[256];
    red[t] = s;
    __syncthreads();
    for (int st = 128; st; st >>= 1) { if (t < st) red[t] += red[t+st]; __syncthreads(); }
    if (t == 0) g_mean[c] = red[0] * (1.f / 16384.f);
}

// ---------------- K2: per-phase body MLP + routing + expert-mix matrices ----------------
__global__ void k_phase(const float* __restrict__ Wb1, const float* __restrict__ bb1,
                        const float* __restrict__ Wb2, const float* __restrict__ bb2,
                        const float* __restrict__ Wr1, const float* __restrict__ br1,
                        const float* __restrict__ Wr2, const float* __restrict__ br2,
                        const float* __restrict__ Wq1, const float* __restrict__ bq1,
                        const float* __restrict__ Wq2, const float* __restrict__ bq2,
                        const float* __restrict__ Wq3, const float* __restrict__ bq3,
                        const float* __restrict__ wcw, const float* __restrict__ wew) {
    int p = blockIdx.x;          // 16 phases
    int ph = p >> 2, pw = p & 3;
    int t = threadIdx.x;         // 256
    __shared__ float s_in[C][4];
    __shared__ float s_h[C][4];
    __shared__ float s_emb[C][4];
    __shared__ float s_r[4];
    __shared__ float s_q1[64];
    __shared__ float s_q2[64];
    __shared__ float s_rw[4];

    float ch = (ph + 0.5f) * 0.25f - 0.5f;
    float cw = (pw + 0.5f) * 0.25f - 0.5f;
    if (t < C) {
        s_in[t][0] = g_mean[t];
        s_in[t][1] = 0.25f;
        s_in[t][2] = ch;
        s_in[t][3] = cw;
    }
    __syncthreads();
    {
        int o = t >> 2, f = t & 3;
        float acc = bb1[o];
        for (int c2 = 0; c2 < C; c2++) acc += Wb1[o*C + c2] * s_in[c2][f];
        s_h[o][f] = fmaxf(acc, 0.f);
    }
    __syncthreads();
    {
        int o = t >> 2, f = t & 3;
        float acc = bb2[o];
        for (int c2 = 0; c2 < C; c2++) acc += Wb2[o*C + c2] * s_h[c2][f];
        float v = fmaxf(acc, 0.f);
        s_emb[o][f] = v;
        g_emb[o][f][p] = v;
    }
    __syncthreads();
    {
        int o = t >> 2, f = t & 3;
        float acc = br1[o];
        for (int c2 = 0; c2 < C; c2++) acc += Wr1[o*C + c2] * s_emb[c2][f];
        s_h[o][f] = fmaxf(acc, 0.f);   // reuse as routing hidden
    }
    __syncthreads();
    if (t < 4) {
        float acc = br2[0];
        for (int o = 0; o < 64; o++) acc += Wr2[o] * s_h[o][t];
        s_r[t] = sigmoidf_(acc);
    }
    __syncthreads();
    if (t < 64) {
        float acc = bq1[t];
        for (int f = 0; f < 4; f++) acc += Wq1[t*4 + f] * s_r[f];
        s_q1[t] = fmaxf(acc, 0.f);
    }
    __syncthreads();
    if (t < 64) {
        float acc = bq2[t];
        for (int i = 0; i < 64; i++) acc += Wq2[t*64 + i] * s_q1[i];
        s_q2[t] = fmaxf(acc, 0.f);
    }
    __syncthreads();
    if (t < 4) {
        float acc = bq3[t];
        for (int o = 0; o < 64; o++) acc += Wq3[t*64 + o] * s_q2[o];
        s_rw[t] = sigmoidf_(acc);
    }
    __syncthreads();
    for (int idx = t; idx < C*KD; idx += 256) {
        int c2 = idx >> 3, k = idx & 7;
        float a1 = 0.f, a2 = 0.f;
        for (int e = 0; e < E; e++) {
            a1 += s_rw[e] * wcw[(e*KD + k)*C + c2];
            a2 += s_rw[e] * wew[(e*C + c2)*KD + k];
        }
        g_M1[p][c2][k] = a1;
        g_M2[p][c2][k] = a2;
    }
}

// ---------------- K3: offset head (per channel) + gather tables ----------------
__global__ void k_off(const float* __restrict__ Wo1, const float* __restrict__ bo1,
                      const float* __restrict__ Wo2, const float* __restrict__ bo2,
                      const float* __restrict__ Wo3, const float* __restrict__ bo3) {
    int c = blockIdx.x;
    int t = threadIdx.x;  // 256
    __shared__ float s_emb[4][NP];
    __shared__ float s_h1[NP][64];
    __shared__ float s_h2[NP][64];
    __shared__ float s_off[NP][2];

    if (t < 64) { int f = t >> 4, p = t & 15; s_emb[f][p] = g_emb[c][f][p]; }
    __syncthreads();
    for (int idx = t; idx < NP*64; idx += 256) {
        int p = idx >> 6, o = idx & 63;
        float acc = bo1[o];
        for (int f = 0; f < 4; f++) acc += Wo1[o*4 + f] * s_emb[f][p];
        s_h1[p][o] = fmaxf(acc, 0.f);
    }
    __syncthreads();
    for (int idx = t; idx < NP*64; idx += 256) {
        int p = idx >> 6, o = idx & 63;
        float acc = bo2[o];
        for (int i = 0; i < 64; i++) acc += Wo2[o*64 + i] * s_h1[p][i];
        s_h2[p][o] = fmaxf(acc, 0.f);
    }
    __syncthreads();
    if (t < 32) {
        int p = t >> 1, j = t & 1;
        float acc = bo3[j];
        for (int o = 0; o < 64; o++) acc += Wo3[j*64 + o] * s_h2[p][o];
        s_off[p][j] = acc;
        g_off[c][p][j] = acc;
    }
    __syncthreads();
    if (t < NP) {
        int p = t;
        int ph = p >> 2, pw = p & 3;
        float tx = (pw + 0.5f) * 0.25f - 0.5f + s_off[p][0];
        float ty = (ph + 0.5f) * 0.25f - 0.5f + s_off[p][1];
        float fx = floorf(tx), fy = floorf(ty);
        int ix = (int)fx, iy = (int)fy;
        float wx = tx - fx, wy = ty - fy;
        g_tabW[p][c] = make_float4((1.f-wy)*(1.f-wx), (1.f-wy)*wx, wy*(1.f-wx), wy*wx);
        g_tabJ[p][c] = ((iy + PAD) * PW + (ix + PAD)) * 4;  // byte offset
        if (ix < -PAD || ix > PAD-1 || iy < -PAD || iy > PAD-1)
            atomicAnd(&g_ok, 0);
    }
}

// ---------------- K4: main fused gather + expert mix ----------------
__global__ __launch_bounds__(256, 2)
void k_main(const float* __restrict__ x, float* __restrict__ out) {
    extern __shared__ char smem[];
    float4* s_W  = (float4*)(smem);                 // [NP][C]    16384 B
    int*    s_J  = (int*)(smem + 16384);            // [NP][C]     4096 B
    float*  s_M1 = (float*)(smem + 20480);          // [NP][C][8] 32768 B
    float*  s_M2 = (float*)(smem + 53248);          // [NP][C][8] 32768 B

    int tid = threadIdx.x;
    {
        const float4* gW = &g_tabW[0][0];
        for (int i = tid; i < NP*C; i += 256) s_W[i] = gW[i];
        const int* gJ = &g_tabJ[0][0];
        for (int i = tid; i < NP*C; i += 256) s_J[i] = gJ[i];
        const float4* gM1 = (const float4*)&g_M1[0][0][0];
        float4* sM1v = (float4*)s_M1;
        for (int i = tid; i < NP*C*2; i += 256) sM1v[i] = gM1[i];
        const float4* gM2 = (const float4*)&g_M2[0][0][0];
        float4* sM2v = (float4*)s_M2;
        for (int i = tid; i < NP*C*2; i += 256) sM2v[i] = gM2[i];
    }
    __syncthreads();

    int blk = blockIdx.x;          // 1024 blocks: (b, h')
    int b  = blk >> 8;
    int hh = blk & 255;
    int ww = tid;                  // 0..255
    int r = hh >> 2, ph = hh & 3, q = ww >> 2, pw = ww & 3;
    int p = ph * 4 + pw;

    float* op = out + ((size_t)b * C * (HS*WSZ) + (size_t)hh * WSZ + ww);

    if (g_ok) {
        const char* base = (const char*)g_xpad
            + ((size_t)b * C * PPLANE + (size_t)r * PW + q) * 4;
        float fea[C];
        unsigned long long mid0 = 0ull, mid1 = 0ull, mid2 = 0ull, mid3 = 0ull;
        const float4* wrow = &s_W[p*C];
        const int*    jrow = &s_J[p*C];
        const ulonglong2* m1row = (const ulonglong2*)&s_M1[p*C*KD];
        const ulonglong2* m2row = (const ulonglong2*)&s_M2[p*C*KD];
        #pragma unroll
        for (int c = 0; c < C; c++) {
            float4 wv = wrow[c];
            int j = jrow[c];
            const float* a = (const float*)(base + j) + c * PPLANE;
            float t00 = __ldg(a);
            float t01 = __ldg(a + 1);
            float t10 = __ldg(a + PW);
            float t11 = __ldg(a + PW + 1);
            float f = t00*wv.x + t01*wv.y + t10*wv.z + t11*wv.w;
            fea[c] = f;
            unsigned long long ff;
            asm("mov.b64 %0, {%1, %1};" : "=l"(ff) : "f"(f));
            ulonglong2 A = m1row[c*2];
            ulonglong2 B = m1row[c*2 + 1];
            fma2(mid0, A.x, ff);
            fma2(mid1, A.y, ff);
            fma2(mid2, B.x, ff);
            fma2(mid3, B.y, ff);
        }
        #pragma unroll
        for (int c = 0; c < C; c++) {
            ulonglong2 A = m2row[c*2];
            ulonglong2 B = m2row[c*2 + 1];
            unsigned long long acc = 0ull;
            fma2(acc, A.x, mid0);
            fma2(acc, A.y, mid1);
            fma2(acc, B.x, mid2);
            fma2(acc, B.y, mid3);
            float lo, hi;
            asm("mov.b64 {%0, %1}, %2;" : "=f"(lo), "=f"(hi) : "l"(acc));
            op[(size_t)c * (HS*WSZ)] = fea[c] + lo + hi;
        }
    } else {
        // general fallback: arbitrary offsets, masked bilinear on original x
        float fea[C];
        float mid[KD];
        for (int k = 0; k < KD; k++) mid[k] = 0.f;
        for (int c = 0; c < C; c++) {
            float offx = g_off[c][p][0];
            float offy = g_off[c][p][1];
            float px = (ww + 0.5f) * 0.25f - 0.5f + offx;
            float py = (hh + 0.5f) * 0.25f - 0.5f + offy;
            float fx = floorf(px), fy = floorf(py);
            int x0 = (int)fx, y0 = (int)fy;
            float wx = px - fx, wy = py - fy;
            const float* pl = x + (size_t)(b*C + c) * (H*W);
            float t00 = 0.f, t01 = 0.f, t10 = 0.f, t11 = 0.f;
            if (y0 >= 0 && y0 <= H-1) {
                if (x0 >= 0 && x0 <= W-1)     t00 = pl[y0*W + x0];
                if (x0+1 >= 0 && x0+1 <= W-1) t01 = pl[y0*W + x0 + 1];
            }
            if (y0+1 >= 0 && y0+1 <= H-1) {
                if (x0 >= 0 && x0 <= W-1)     t10 = pl[(y0+1)*W + x0];
                if (x0+1 >= 0 && x0+1 <= W-1) t11 = pl[(y0+1)*W + x0 + 1];
            }
            float f = t00*(1.f-wy)*(1.f-wx) + t01*(1.f-wy)*wx + t10*wy*(1.f-wx) + t11*wy*wx;
            fea[c] = f;
            for (int k = 0; k < KD; k++) mid[k] += s_M1[(p*C + c)*KD + k] * f;
        }
        for (int c = 0; c < C; c++) {
            float acc = 0.f;
            for (int k = 0; k < KD; k++) acc += s_M2[(p*C + c)*KD + k] * mid[k];
            op[(size_t)c * (HS*WSZ)] = fea[c] + acc;
        }
    }
}

// ---------------- launch ----------------
extern "C" void kernel_launch(void* const* d_in, const int* in_sizes, int n_in,
                              void* d_out, int out_size) {
    const float* x   = (const float*)d_in[0];
    const float* wcw = (const float*)d_in[1];
    const float* wew = (const float*)d_in[2];
    const float* Wb1 = (const float*)d_in[3];
    const float* bb1 = (const float*)d_in[4];
    const float* Wb2 = (const float*)d_in[5];
    const float* bb2 = (const float*)d_in[6];
    const float* Wr1 = (const float*)d_in[7];
    const float* br1 = (const float*)d_in[8];
    const float* Wr2 = (const float*)d_in[9];
    const float* br2 = (const float*)d_in[10];
    const float* Wq1 = (const float*)d_in[11];
    const float* bq1 = (const float*)d_in[12];
    const float* Wq2 = (const float*)d_in[13];
    const float* bq2 = (const float*)d_in[14];
    const float* Wq3 = (const float*)d_in[15];
    const float* bq3 = (const float*)d_in[16];
    const float* Wo1 = (const float*)d_in[17];
    const float* bo1 = (const float*)d_in[18];
    const float* Wo2 = (const float*)d_in[19];
    const float* bo2 = (const float*)d_in[20];
    const float* Wo3 = (const float*)d_in[21];
    const float* bo3 = (const float*)d_in[22];
    float* out = (float*)d_out;

    static bool attr_set = false;
    (void)attr_set;
    cudaFuncSetAttribute(k_main, cudaFuncAttributeMaxDynamicSharedMemorySize, 86016);

    k_pad<<<(BS*C*PPLANE + 255)/256, 256>>>(x);
    k_mean<<<C, 256>>>(x);
    k_phase<<<NP, 256>>>(Wb1, bb1, Wb2, bb2, Wr1, br1, Wr2, br2,
                         Wq1, bq1, Wq2, bq2, Wq3, bq3, wcw, wew);
    k_off<<<C, 256>>>(Wo1, bo1, Wo2, bo2, Wo3, bo3);
    k_main<<<BS*HS, 256, 86016>>>(x, out);
}

// round 8
// speedup vs baseline: 1.7932x; 1.7932x over previous
#include <cuda_runtime.h>
#include <cstdint>
#include <cstddef>

#define BS 4
#define C 64
#define H 64
#define W 64
#define HS 256
#define WSZ 256
#define E 4
#define KD 8
#define PAD 8
#define PW 80
#define PPLANE (PW*PW)
#define NP 16

// ---------------- device globals (static scratch; no allocation) ----------------
__device__ float g_xpad[BS*C*PPLANE];     // zero-padded input, [b][c][80][80]
__device__ float g_mean[C];
__device__ float g_emb[C][4][NP];         // emb[c][f][p]
__device__ float g_M1[NP][C][KD];         // per-phase compress  mid[k] += M1[p][c][k]*fea
__device__ float g_M2[NP][C][KD];         // per-phase expand    out[c] += M2[p][c][k]*mid[k]
__device__ float4 g_tabW[NP][C];          // bilinear weights (w00,w01,w10,w11)
__device__ int    g_tabJ[NP][C];          // byte offset into padded plane
__device__ float  g_off[C][NP][2];        // raw offsets (fallback path)
__device__ int    g_ok;

__device__ __forceinline__ float sigmoidf_(float v) { return 1.f / (1.f + expf(-v)); }

__device__ __forceinline__ void fma2(unsigned long long &d, unsigned long long a, unsigned long long b) {
    asm("fma.rn.f32x2 %0, %1, %2, %0;" : "+l"(d) : "l"(a), "l"(b));
}

// ---------------- K0: zero-pad x into g_xpad, reset flag ----------------
__global__ void k_pad(const float* __restrict__ x) {
    int i = blockIdx.x * 256 + threadIdx.x;
    if (i == 0) g_ok = 1;
    if (i >= BS*C*PPLANE) return;
    int xx = i % PW;
    int rest = i / PW;
    int yy = rest % PW;
    int bc = rest / PW;
    float v = 0.f;
    if (yy >= PAD && yy < PAD + H && xx >= PAD && xx < PAD + W)
        v = x[(size_t)bc * (H*W) + (yy - PAD) * W + (xx - PAD)];
    g_xpad[i] = v;
}

// ---------------- K1: per-channel mean of x over (b,h,w) ----------------
__global__ void k_mean(const float* __restrict__ x) {
    int c = blockIdx.x;
    int t = threadIdx.x;
    float s = 0.f;
    for (int b = 0; b < BS; b++) {
        const float* pl = x + (size_t)(b*C + c) * (H*W);
        for (int i = t; i < H*W; i += 256) s += pl[i];
    }
    __shared__ float red[256];
    red[t] = s;
    __syncthreads();
    for (int st = 128; st; st >>= 1) { if (t < st) red[t] += red[t+st]; __syncthreads(); }
    if (t == 0) g_mean[c] = red[0] * (1.f / 16384.f);
}

// ---------------- K2: per-phase body MLP + routing + expert-mix matrices ----------------
// dynamic smem: s_b1[64][65], s_b2[64][65], s_r1[64][65]  (padded, conflict-free)
__global__ void k_phase(const float* __restrict__ Wb1, const float* __restrict__ bb1,
                        const float* __restrict__ Wb2, const float* __restrict__ bb2,
                        const float* __restrict__ Wr1, const float* __restrict__ br1,
                        const float* __restrict__ Wr2, const float* __restrict__ br2,
                        const float* __restrict__ Wq1, const float* __restrict__ bq1,
                        const float* __restrict__ Wq2, const float* __restrict__ bq2,
                        const float* __restrict__ Wq3, const float* __restrict__ bq3,
                        const float* __restrict__ wcw, const float* __restrict__ wew) {
    extern __shared__ float dyn[];
    float* s_b1 = dyn;                // [64][65]
    float* s_b2 = dyn + 64*65;        // [64][65]
    float* s_r1 = dyn + 2*64*65;      // [64][65]

    int p = blockIdx.x;          // 16 phases
    int ph = p >> 2, pw = p & 3;
    int t = threadIdx.x;         // 256
    __shared__ float s_in[C][4];
    __shared__ float s_h[C][4];
    __shared__ float s_emb[C][4];
    __shared__ float s_r[4];
    __shared__ float s_q1[64];
    __shared__ float s_q2[64];
    __shared__ float s_rw[4];

    // cache weight matrices
    for (int i = t; i < 64*64; i += 256) {
        int o = i >> 6, cc = i & 63;
        s_b1[o*65 + cc] = Wb1[i];
        s_b2[o*65 + cc] = Wb2[i];
        s_r1[o*65 + cc] = Wr1[i];
    }

    float ch = (ph + 0.5f) * 0.25f - 0.5f;
    float cw = (pw + 0.5f) * 0.25f - 0.5f;
    if (t < C) {
        s_in[t][0] = g_mean[t];
        s_in[t][1] = 0.25f;
        s_in[t][2] = ch;
        s_in[t][3] = cw;
    }
    __syncthreads();
    {
        int o = t >> 2, f = t & 3;
        float acc = bb1[o];
        #pragma unroll 16
        for (int c2 = 0; c2 < C; c2++) acc += s_b1[o*65 + c2] * s_in[c2][f];
        s_h[o][f] = fmaxf(acc, 0.f);
    }
    __syncthreads();
    {
        int o = t >> 2, f = t & 3;
        float acc = bb2[o];
        #pragma unroll 16
        for (int c2 = 0; c2 < C; c2++) acc += s_b2[o*65 + c2] * s_h[c2][f];
        float v = fmaxf(acc, 0.f);
        s_emb[o][f] = v;
        g_emb[o][f][p] = v;
    }
    __syncthreads();
    {
        int o = t >> 2, f = t & 3;
        float acc = br1[o];
        #pragma unroll 16
        for (int c2 = 0; c2 < C; c2++) acc += s_r1[o*65 + c2] * s_emb[c2][f];
        s_h[o][f] = fmaxf(acc, 0.f);   // routing hidden
    }
    __syncthreads();
    if (t < 4) {
        float acc = br2[0];
        #pragma unroll 16
        for (int o = 0; o < 64; o++) acc += __ldg(Wr2 + o) * s_h[o][t];
        s_r[t] = sigmoidf_(acc);
    }
    __syncthreads();
    if (t < 64) {
        float acc = bq1[t];
        #pragma unroll
        for (int f = 0; f < 4; f++) acc += Wq1[t*4 + f] * s_r[f];
        s_q1[t] = fmaxf(acc, 0.f);
    }
    __syncthreads();
    if (t < 64) {
        float acc = bq2[t];
        #pragma unroll 16
        for (int i = 0; i < 64; i++) acc += __ldg(Wq2 + t*64 + i) * s_q1[i];
        s_q2[t] = fmaxf(acc, 0.f);
    }
    __syncthreads();
    if (t < 4) {
        float acc = bq3[t];
        #pragma unroll 16
        for (int o = 0; o < 64; o++) acc += __ldg(Wq3 + t*64 + o) * s_q2[o];
        s_rw[t] = sigmoidf_(acc);
    }
    __syncthreads();
    for (int idx = t; idx < C*KD; idx += 256) {
        int c2 = idx >> 3, k = idx & 7;
        float a1 = 0.f, a2 = 0.f;
        #pragma unroll
        for (int e = 0; e < E; e++) {
            a1 += s_rw[e] * wcw[(e*KD + k)*C + c2];
            a2 += s_rw[e] * wew[(e*C + c2)*KD + k];
        }
        g_M1[p][c2][k] = a1;
        g_M2[p][c2][k] = a2;
    }
}

// ---------------- K3: offset head (per channel) + gather tables ----------------
__global__ void k_off(const float* __restrict__ Wo1, const float* __restrict__ bo1,
                      const float* __restrict__ Wo2, const float* __restrict__ bo2,
                      const float* __restrict__ Wo3, const float* __restrict__ bo3) {
    int c = blockIdx.x;
    int t = threadIdx.x;  // 256
    __shared__ float s_emb[4][NP];
    __shared__ float s_w2[64*65];     // padded Wo2 cache (16.6KB)
    __shared__ float s_h1[NP][64];
    __shared__ float s_h2[NP][64];
    __shared__ float s_off[NP][2];

    for (int i = t; i < 64*64; i += 256) {
        int o = i >> 6, ii = i & 63;
        s_w2[o*65 + ii] = Wo2[i];
    }
    if (t < 64) { int f = t >> 4, p = t & 15; s_emb[f][p] = g_emb[c][f][p]; }
    __syncthreads();
    for (int idx = t; idx < NP*64; idx += 256) {
        int p = idx >> 6, o = idx & 63;
        float acc = bo1[o];
        #pragma unroll
        for (int f = 0; f < 4; f++) acc += Wo1[o*4 + f] * s_emb[f][p];
        s_h1[p][o] = fmaxf(acc, 0.f);
    }
    __syncthreads();
    for (int idx = t; idx < NP*64; idx += 256) {
        int p = idx >> 6, o = idx & 63;
        float acc = bo2[o];
        #pragma unroll 16
        for (int i = 0; i < 64; i++) acc += s_w2[o*65 + i] * s_h1[p][i];
        s_h2[p][o] = fmaxf(acc, 0.f);
    }
    __syncthreads();
    if (t < 32) {
        int p = t >> 1, j = t & 1;
        float acc = bo3[j];
        #pragma unroll 16
        for (int o = 0; o < 64; o++) acc += __ldg(Wo3 + j*64 + o) * s_h2[p][o];
        s_off[p][j] = acc;
        g_off[c][p][j] = acc;
    }
    __syncthreads();
    if (t < NP) {
        int p = t;
        int ph = p >> 2, pw = p & 3;
        float tx = (pw + 0.5f) * 0.25f - 0.5f + s_off[p][0];
        float ty = (ph + 0.5f) * 0.25f - 0.5f + s_off[p][1];
        float fx = floorf(tx), fy = floorf(ty);
        int ix = (int)fx, iy = (int)fy;
        float wx = tx - fx, wy = ty - fy;
        g_tabW[p][c] = make_float4((1.f-wy)*(1.f-wx), (1.f-wy)*wx, wy*(1.f-wx), wy*wx);
        g_tabJ[p][c] = ((iy + PAD) * PW + (ix + PAD)) * 4;  // byte offset
        if (ix < -PAD || ix > PAD-1 || iy < -PAD || iy > PAD-1)
            atomicAnd(&g_ok, 0);
    }
}

// ---------------- K4: main fused gather + expert mix (phase-major, smem fea) ----------------
// dyn smem layout:
//   s_W  [4][C] float4    @ 0        (4096 B)
//   s_J  [4][C] int       @ 4096     (1024 B)
//   s_M1 [4][C][8] float  @ 5120     (8192 B)
//   s_M2 [4][C][8] float  @ 13312    (8192 B)
//   s_fea[C][256] float   @ 21504    (65536 B)
// total 87040 B
__global__ __launch_bounds__(256, 2)
void k_main(const float* __restrict__ x, float* __restrict__ out) {
    extern __shared__ char smem[];
    float4* s_W  = (float4*)(smem);
    int*    s_J  = (int*)(smem + 4096);
    float*  s_M1 = (float*)(smem + 5120);
    float*  s_M2 = (float*)(smem + 13312);
    float*  s_fea = (float*)(smem + 21504);

    int tid = threadIdx.x;
    int blk = blockIdx.x;          // 1024 blocks: (b, h')
    int b  = blk >> 8;
    int hh = blk & 255;
    int r  = hh >> 2;
    int ph = hh & 3;

    // preload tables for this block's 4 phases (contiguous from phase ph*4)
    {
        const float4* gW = &g_tabW[ph*4][0];                 // 256 float4
        s_W[tid] = gW[tid];
        const int* gJ = &g_tabJ[ph*4][0];                    // 256 ints
        s_J[tid] = gJ[tid];
        const float4* gM1 = (const float4*)&g_M1[ph*4][0][0];// 512 float4
        float4* sM1v = (float4*)s_M1;
        sM1v[tid] = gM1[tid];
        sM1v[tid + 256] = gM1[tid + 256];
        const float4* gM2 = (const float4*)&g_M2[ph*4][0][0];
        float4* sM2v = (float4*)s_M2;
        sM2v[tid] = gM2[tid];
        sM2v[tid + 256] = gM2[tid + 256];
    }
    __syncthreads();

    // phase-major mapping: warp-uniform phase, coalesced gathers
    int pw = tid >> 6;             // 0..3 (uniform within warp)
    int q  = tid & 63;             // 0..63
    int ww = q * 4 + pw;           // pixel column
    int sidx = pw * 64 + (q ^ (pw * 8));   // swizzled smem pixel slot (conflict-free)

    if (g_ok) {
        const char* base = (const char*)g_xpad
            + ((size_t)b * C * PPLANE + (size_t)r * PW + q) * 4;
        unsigned long long mid0 = 0ull, mid1 = 0ull, mid2 = 0ull, mid3 = 0ull;
        const float4* wrow = &s_W[pw*C];
        const int*    jrow = &s_J[pw*C];
        const ulonglong2* m1row = (const ulonglong2*)&s_M1[pw*C*KD];
        const ulonglong2* m2row = (const ulonglong2*)&s_M2[pw*C*KD];

        // pass 1: gather fea -> smem, accumulate mid (packed f32x2)
        #pragma unroll 8
        for (int c = 0; c < C; c++) {
            float4 wv = wrow[c];               // warp-uniform broadcast
            int j = jrow[c];
            const float* a = (const float*)(base + j) + c * PPLANE;
            float t00 = __ldg(a);
            float t01 = __ldg(a + 1);
            float t10 = __ldg(a + PW);
            float t11 = __ldg(a + PW + 1);
            float f = t00*wv.x + t01*wv.y + t10*wv.z + t11*wv.w;
            s_fea[c*256 + sidx] = f;
            unsigned long long ff;
            asm("mov.b64 %0, {%1, %1};" : "=l"(ff) : "f"(f));
            ulonglong2 A = m1row[c*2];
            ulonglong2 B = m1row[c*2 + 1];
            fma2(mid0, A.x, ff);
            fma2(mid1, A.y, ff);
            fma2(mid2, B.x, ff);
            fma2(mid3, B.y, ff);
        }

        // pass 2: per-channel mix, write result back into own smem slot
        #pragma unroll 8
        for (int c = 0; c < C; c++) {
            ulonglong2 A = m2row[c*2];
            ulonglong2 B = m2row[c*2 + 1];
            unsigned long long acc = 0ull;
            fma2(acc, A.x, mid0);
            fma2(acc, A.y, mid1);
            fma2(acc, B.x, mid2);
            fma2(acc, B.y, mid3);
            float lo, hi;
            asm("mov.b64 {%0, %1}, %2;" : "=f"(lo), "=f"(hi) : "l"(acc));
            s_fea[c*256 + sidx] += lo + hi;
        }
        __syncthreads();

        // pass 3: transposed read (conflict-free via swizzle), coalesced store
        int pw2 = tid & 3;
        int q2  = tid >> 2;
        int ridx = pw2 * 64 + (q2 ^ (pw2 * 8));
        float* op = out + ((size_t)b * C * (HS*WSZ) + (size_t)hh * WSZ + tid);
        #pragma unroll 8
        for (int c = 0; c < C; c++) {
            op[(size_t)c * (HS*WSZ)] = s_fea[c*256 + ridx];
        }
    } else {
        // general fallback: arbitrary offsets, masked bilinear on original x
        int p = ph * 4 + pw;
        float fea[C];
        float mid[KD];
        for (int k = 0; k < KD; k++) mid[k] = 0.f;
        float* op = out + ((size_t)b * C * (HS*WSZ) + (size_t)hh * WSZ + ww);
        for (int c = 0; c < C; c++) {
            float offx = g_off[c][p][0];
            float offy = g_off[c][p][1];
            float px = (ww + 0.5f) * 0.25f - 0.5f + offx;
            float py = (hh + 0.5f) * 0.25f - 0.5f + offy;
            float fx = floorf(px), fy = floorf(py);
            int x0 = (int)fx, y0 = (int)fy;
            float wx = px - fx, wy = py - fy;
            const float* pl = x + (size_t)(b*C + c) * (H*W);
            float t00 = 0.f, t01 = 0.f, t10 = 0.f, t11 = 0.f;
            if (y0 >= 0 && y0 <= H-1) {
                if (x0 >= 0 && x0 <= W-1)     t00 = pl[y0*W + x0];
                if (x0+1 >= 0 && x0+1 <= W-1) t01 = pl[y0*W + x0 + 1];
            }
            if (y0+1 >= 0 && y0+1 <= H-1) {
                if (x0 >= 0 && x0 <= W-1)     t10 = pl[(y0+1)*W + x0];
                if (x0+1 >= 0 && x0+1 <= W-1) t11 = pl[(y0+1)*W + x0 + 1];
            }
            float f = t00*(1.f-wy)*(1.f-wx) + t01*(1.f-wy)*wx + t10*wy*(1.f-wx) + t11*wy*wx;
            fea[c] = f;
            for (int k = 0; k < KD; k++) mid[k] += s_M1[(pw*C + c)*KD + k] * f;
        }
        for (int c = 0; c < C; c++) {
            float acc = 0.f;
            for (int k = 0; k < KD; k++) acc += s_M2[(pw*C + c)*KD + k] * mid[k];
            op[(size_t)c * (HS*WSZ)] = fea[c] + acc;
        }
    }
}

// ---------------- launch ----------------
extern "C" void kernel_launch(void* const* d_in, const int* in_sizes, int n_in,
                              void* d_out, int out_size) {
    const float* x   = (const float*)d_in[0];
    const float* wcw = (const float*)d_in[1];
    const float* wew = (const float*)d_in[2];
    const float* Wb1 = (const float*)d_in[3];
    const float* bb1 = (const float*)d_in[4];
    const float* Wb2 = (const float*)d_in[5];
    const float* bb2 = (const float*)d_in[6];
    const float* Wr1 = (const float*)d_in[7];
    const float* br1 = (const float*)d_in[8];
    const float* Wr2 = (const float*)d_in[9];
    const float* br2 = (const float*)d_in[10];
    const float* Wq1 = (const float*)d_in[11];
    const float* bq1 = (const float*)d_in[12];
    const float* Wq2 = (const float*)d_in[13];
    const float* bq2 = (const float*)d_in[14];
    const float* Wq3 = (const float*)d_in[15];
    const float* bq3 = (const float*)d_in[16];
    const float* Wo1 = (const float*)d_in[17];
    const float* bo1 = (const float*)d_in[18];
    const float* Wo2 = (const float*)d_in[19];
    const float* bo2 = (const float*)d_in[20];
    const float* Wo3 = (const float*)d_in[21];
    const float* bo3 = (const float*)d_in[22];
    float* out = (float*)d_out;

    const int PHASE_SMEM = 3 * 64 * 65 * 4;  // 49920 B
    cudaFuncSetAttribute(k_phase, cudaFuncAttributeMaxDynamicSharedMemorySize, PHASE_SMEM);
    cudaFuncSetAttribute(k_main, cudaFuncAttributeMaxDynamicSharedMemorySize, 87040);

    k_pad<<<(BS*C*PPLANE + 255)/256, 256>>>(x);
    k_mean<<<C, 256>>>(x);
    k_phase<<<NP, 256, PHASE_SMEM>>>(Wb1, bb1, Wb2, bb2, Wr1, br1, Wr2, br2,
                                     Wq1, bq1, Wq2, bq2, Wq3, bq3, wcw, wew);
    k_off<<<C, 256>>>(Wo1, bo1, Wo2, bo2, Wo3, bo3);
    k_main<<<BS*HS, 256, 87040>>>(x, out);
}

// round 15
// speedup vs baseline: 1.9542x; 1.0898x over previous
#include <cuda_runtime.h>
#include <cstdint>
#include <cstddef>

#define BS 4
#define C 64
#define H 64
#define W 64
#define HS 256
#define WSZ 256
#define E 4
#define KD 8
#define PAD 8
#define PW 80
#define PPLANE (PW*PW)
#define NP 16

// pad work: BS*C*PPLANE = 1,638,400 elems = 6400 blocks of 256
#define PAD_BLOCKS ((BS*C*PPLANE)/256)

// ---------------- device globals (static scratch; no allocation) ----------------
__device__ float g_xpad[BS*C*PPLANE];     // zero-padded input, [b][c][80][80]
__device__ float g_mean[C];
__device__ float g_M1[NP][C][KD];         // per-phase compress  mid[k] += M1[p][c][k]*fea
__device__ float g_M2[NP][C][KD];         // per-phase expand    out[c] += M2[p][c][k]*mid[k]
__device__ float4 g_tabW[NP][C];          // bilinear weights (w00,w01,w10,w11)
__device__ int    g_tabJ[NP][C];          // byte offset into padded plane
__device__ float  g_off[C][NP][2];        // raw offsets (fallback path)
__device__ int    g_ok;

__device__ __forceinline__ float sigmoidf_(float v) { return 1.f / (1.f + expf(-v)); }

__device__ __forceinline__ void fma2(unsigned long long &d, unsigned long long a, unsigned long long b) {
    asm("fma.rn.f32x2 %0, %1, %2, %0;" : "+l"(d) : "l"(a), "l"(b));
}

// ---------------- K1: zero-pad x into g_xpad + per-channel mean, one launch ----------------
// blocks [0,PAD_BLOCKS): pad.  blocks [PAD_BLOCKS, PAD_BLOCKS+64): mean per channel.
__global__ void k_prep(const float* __restrict__ x) {
    int blk = blockIdx.x;
    int t = threadIdx.x;
    if (blk < PAD_BLOCKS) {
        int i = blk * 256 + t;
        if (i == 0) g_ok = 1;
        int xx = i % PW;
        int rest = i / PW;
        int yy = rest % PW;
        int bc = rest / PW;
        float v = 0.f;
        if (yy >= PAD && yy < PAD + H && xx >= PAD && xx < PAD + W)
            v = x[(size_t)bc * (H*W) + (yy - PAD) * W + (xx - PAD)];
        g_xpad[i] = v;
    } else {
        int c = blk - PAD_BLOCKS;
        float s = 0.f;
        for (int b = 0; b < BS; b++) {
            const float* pl = x + (size_t)(b*C + c) * (H*W);
            for (int i = t; i < H*W; i += 256) s += pl[i];
        }
        __shared__ float red[256];
        red[t] = s;
        __syncthreads();
        for (int st = 128; st; st >>= 1) { if (t < st) red[t] += red[t+st]; __syncthreads(); }
        if (t == 0) g_mean[c] = red[0] * (1.f / 16384.f);
    }
}

// ---------------- K2: fused emb (6-variant trick) + offset head + routing ----------------
// grid = 80 blocks, 256 threads.
// blocks 0..63 : offset head + gather tables for channel c = blk
// blocks 64..79: routing + expert-mix M1/M2 for phase p = blk-64
__global__ void k_pre2(const float* __restrict__ Wb1, const float* __restrict__ bb1,
                       const float* __restrict__ Wb2, const float* __restrict__ bb2,
                       const float* __restrict__ Wr1, const float* __restrict__ br1,
                       const float* __restrict__ Wr2, const float* __restrict__ br2,
                       const float* __restrict__ Wq1, const float* __restrict__ bq1,
                       const float* __restrict__ Wq2, const float* __restrict__ bq2,
                       const float* __restrict__ Wq3, const float* __restrict__ bq3,
                       const float* __restrict__ wcw, const float* __restrict__ wew,
                       const float* __restrict__ Wo1, const float* __restrict__ bo1,
                       const float* __restrict__ Wo2, const float* __restrict__ bo2,
                       const float* __restrict__ Wo3, const float* __restrict__ bo3) {
    extern __shared__ float dyn[];
    float* sW_a   = dyn;               // 4160
    float* sW_b   = dyn + 4160;        // 4160
    float* s_h1v  = dyn + 8320;        // 512
    float* s_embv = dyn + 8832;        // 512
    float* s_misc = dyn + 9344;        // 512

    int blk = blockIdx.x;
    int t = threadIdx.x;

    // stage 1: cache Wb1, Wb2 (padded), mean
    for (int i = t; i < 64*64; i += 256) {
        int o = i >> 6, cc = i & 63;
        sW_a[o*65 + cc] = Wb1[i];
        sW_b[o*65 + cc] = Wb2[i];
    }
    if (t < 64) s_misc[t] = g_mean[t];
    __syncthreads();

    // stage 2: layer-1 hidden for 6 variants.
    // variant 0: input = mean[c];  1: const 0.25;  2+j: const (j+0.5)*0.25-0.5
    if (t < 64) {
        int o = t;
        float rs = 0.f, dm = 0.f;
        #pragma unroll 16
        for (int c2 = 0; c2 < C; c2++) {
            float wv = sW_a[o*65 + c2];
            rs += wv;
            dm += wv * s_misc[c2];
        }
        float b = bb1[o];
        s_h1v[o*8 + 0] = fmaxf(b + dm, 0.f);
        s_h1v[o*8 + 1] = fmaxf(b + 0.25f*rs, 0.f);
        #pragma unroll
        for (int j = 0; j < 4; j++) {
            float kap = (j + 0.5f) * 0.25f - 0.5f;
            s_h1v[o*8 + 2 + j] = fmaxf(b + kap*rs, 0.f);
        }
    }
    __syncthreads();

    // stage 3: layer-2 -> emb variants (6 matvecs) — strided: 384 items, 256 threads
    for (int idx = t; idx < 6*64; idx += 256) {
        int v = idx >> 6, o = idx & 63;
        float acc = bb2[o];
        #pragma unroll 16
        for (int c2 = 0; c2 < C; c2++) acc += sW_b[o*65 + c2] * s_h1v[c2*8 + v];
        s_embv[o*8 + v] = fmaxf(acc, 0.f);
    }
    __syncthreads();

    if (blk < 64) {
        // ---- Role A: offset head for channel c = blk ----
        int c = blk;
        // recache: Wo2 into sW_a
        for (int i = t; i < 64*64; i += 256) {
            int o = i >> 6, ii = i & 63;
            sW_a[o*65 + ii] = Wo2[i];
        }
        float* s_h1o = sW_b;          // [16][64]
        float* s_h2o = sW_b + 1024;   // [16][64]
        float* s_off = s_misc + 320;  // [16][2]
        // emb vec components for this channel
        float e0 = s_embv[c*8 + 0];
        float e1 = s_embv[c*8 + 1];
        // layer 1 of offset head
        for (int idx = t; idx < NP*64; idx += 256) {
            int p = idx >> 6, o = idx & 63;
            int ph = p >> 2, pw = p & 3;
            float e2 = s_embv[c*8 + 2 + ph];
            float e3 = s_embv[c*8 + 2 + pw];
            float acc = bo1[o]
                + __ldg(Wo1 + o*4 + 0) * e0
                + __ldg(Wo1 + o*4 + 1) * e1
                + __ldg(Wo1 + o*4 + 2) * e2
                + __ldg(Wo1 + o*4 + 3) * e3;
            s_h1o[p*64 + o] = fmaxf(acc, 0.f);
        }
        __syncthreads();
        for (int idx = t; idx < NP*64; idx += 256) {
            int p = idx >> 6, o = idx & 63;
            float acc = bo2[o];
            #pragma unroll 16
            for (int i = 0; i < 64; i++) acc += sW_a[o*65 + i] * s_h1o[p*64 + i];
            s_h2o[p*64 + o] = fmaxf(acc, 0.f);
        }
        __syncthreads();
        if (t < 32) {
            int p = t >> 1, j = t & 1;
            float acc = bo3[j];
            #pragma unroll 16
            for (int o = 0; o < 64; o++) acc += __ldg(Wo3 + j*64 + o) * s_h2o[p*64 + o];
            s_off[p*2 + j] = acc;
            g_off[c][p][j] = acc;
        }
        __syncthreads();
        if (t < NP) {
            int p = t;
            int ph = p >> 2, pw = p & 3;
            float tx = (pw + 0.5f) * 0.25f - 0.5f + s_off[p*2 + 0];
            float ty = (ph + 0.5f) * 0.25f - 0.5f + s_off[p*2 + 1];
            float fx = floorf(tx), fy = floorf(ty);
            int ix = (int)fx, iy = (int)fy;
            float wx = tx - fx, wy = ty - fy;
            g_tabW[p][c] = make_float4((1.f-wy)*(1.f-wx), (1.f-wy)*wx, wy*(1.f-wx), wy*wx);
            g_tabJ[p][c] = ((iy + PAD) * PW + (ix + PAD)) * 4;  // byte offset
            if (ix < -PAD || ix > PAD-1 || iy < -PAD || iy > PAD-1)
                atomicAnd(&g_ok, 0);
        }
    } else {
        // ---- Role B: routing + M1/M2 for phase p = blk-64 ----
        int p = blk - 64;
        int ph = p >> 2, pwp = p & 3;
        // recache: Wr1 into sW_a
        for (int i = t; i < 64*64; i += 256) {
            int o = i >> 6, cc = i & 63;
            sW_a[o*65 + cc] = Wr1[i];
        }
        float* s_rh = s_misc + 64;    // [64][4]
        float* s_r  = s_misc + 320;   // [4]
        float* s_q1 = s_misc + 324;   // [64]
        float* s_q2 = s_misc + 388;   // [64]
        float* s_rw = s_misc + 452;   // [4]
        __syncthreads();
        {
            int o = t >> 2, f = t & 3;
            int mf = (f == 0) ? 0 : (f == 1) ? 1 : (f == 2) ? (2 + ph) : (2 + pwp);
            float acc = br1[o];
            #pragma unroll 16
            for (int c2 = 0; c2 < C; c2++) acc += sW_a[o*65 + c2] * s_embv[c2*8 + mf];
            s_rh[o*4 + f] = fmaxf(acc, 0.f);
        }
        __syncthreads();
        if (t < 4) {
            float acc = br2[0];
            #pragma unroll 16
            for (int o = 0; o < 64; o++) acc += __ldg(Wr2 + o) * s_rh[o*4 + t];
            s_r[t] = sigmoidf_(acc);
        }
        __syncthreads();
        if (t < 64) {
            float acc = bq1[t];
            #pragma unroll
            for (int f = 0; f < 4; f++) acc += __ldg(Wq1 + t*4 + f) * s_r[f];
            s_q1[t] = fmaxf(acc, 0.f);
        }
        __syncthreads();
        if (t < 64) {
            float acc = bq2[t];
            #pragma unroll 16
            for (int i = 0; i < 64; i++) acc += __ldg(Wq2 + t*64 + i) * s_q1[i];
            s_q2[t] = fmaxf(acc, 0.f);
        }
        __syncthreads();
        if (t < 4) {
            float acc = bq3[t];
            #pragma unroll 16
            for (int o = 0; o < 64; o++) acc += __ldg(Wq3 + t*64 + o) * s_q2[o];
            s_rw[t] = sigmoidf_(acc);
        }
        __syncthreads();
        for (int idx = t; idx < C*KD; idx += 256) {
            int c2 = idx >> 3, k = idx & 7;
            float a1 = 0.f, a2 = 0.f;
            #pragma unroll
            for (int e = 0; e < E; e++) {
                a1 += s_rw[e] * wcw[(e*KD + k)*C + c2];
                a2 += s_rw[e] * wew[(e*C + c2)*KD + k];
            }
            g_M1[p][c2][k] = a1;
            g_M2[p][c2][k] = a2;
        }
    }
}

// ---------------- K3: main fused gather + expert mix (phase-major, smem fea) ----------------
// dyn smem layout:
//   s_W  [4][C] float4    @ 0        (4096 B)
//   s_J  [4][C] int       @ 4096     (1024 B)
//   s_M1 [4][C][8] float  @ 5120     (8192 B)
//   s_M2 [4][C][8] float  @ 13312    (8192 B)
//   s_fea[C][256] float   @ 21504    (65536 B)
// total 87040 B
__global__ __launch_bounds__(256, 2)
void k_main(const float* __restrict__ x, float* __restrict__ out) {
    extern __shared__ char smem[];
    float4* s_W  = (float4*)(smem);
    int*    s_J  = (int*)(smem + 4096);
    float*  s_M1 = (float*)(smem + 5120);
    float*  s_M2 = (float*)(smem + 13312);
    float*  s_fea = (float*)(smem + 21504);

    int tid = threadIdx.x;
    int blk = blockIdx.x;          // 1024 blocks: (b, h')
    int b  = blk >> 8;
    int hh = blk & 255;
    int r  = hh >> 2;
    int ph = hh & 3;

    // preload tables for this block's 4 phases (contiguous from phase ph*4)
    {
        const float4* gW = &g_tabW[ph*4][0];                 // 256 float4
        s_W[tid] = gW[tid];
        const int* gJ = &g_tabJ[ph*4][0];                    // 256 ints
        s_J[tid] = gJ[tid];
        const float4* gM1 = (const float4*)&g_M1[ph*4][0][0];// 512 float4
        float4* sM1v = (float4*)s_M1;
        sM1v[tid] = gM1[tid];
        sM1v[tid + 256] = gM1[tid + 256];
        const float4* gM2 = (const float4*)&g_M2[ph*4][0][0];
        float4* sM2v = (float4*)s_M2;
        sM2v[tid] = gM2[tid];
        sM2v[tid + 256] = gM2[tid + 256];
    }
    __syncthreads();

    // phase-major mapping: warp-uniform phase, coalesced gathers
    int pw = tid >> 6;             // 0..3 (uniform within warp)
    int q  = tid & 63;             // 0..63
    int ww = q * 4 + pw;           // pixel column
    int sidx = pw * 64 + (q ^ (pw * 8));   // swizzled smem pixel slot (conflict-free)

    if (g_ok) {
        const char* base = (const char*)g_xpad
            + ((size_t)b * C * PPLANE + (size_t)r * PW + q) * 4;
        unsigned long long mid0 = 0ull, mid1 = 0ull, mid2 = 0ull, mid3 = 0ull;
        const float4* wrow = &s_W[pw*C];
        const int*    jrow = &s_J[pw*C];
        const ulonglong2* m1row = (const ulonglong2*)&s_M1[pw*C*KD];
        const ulonglong2* m2row = (const ulonglong2*)&s_M2[pw*C*KD];

        // pass 1: gather fea -> smem, accumulate mid (packed f32x2)
        #pragma unroll 8
        for (int c = 0; c < C; c++) {
            float4 wv = wrow[c];               // warp-uniform broadcast
            int j = jrow[c];
            const float* a = (const float*)(base + j) + c * PPLANE;
            float t00 = __ldg(a);
            float t01 = __ldg(a + 1);
            float t10 = __ldg(a + PW);
            float t11 = __ldg(a + PW + 1);
            float f = t00*wv.x + t01*wv.y + t10*wv.z + t11*wv.w;
            s_fea[c*256 + sidx] = f;
            unsigned long long ff;
            asm("mov.b64 %0, {%1, %1};" : "=l"(ff) : "f"(f));
            ulonglong2 A = m1row[c*2];
            ulonglong2 B = m1row[c*2 + 1];
            fma2(mid0, A.x, ff);
            fma2(mid1, A.y, ff);
            fma2(mid2, B.x, ff);
            fma2(mid3, B.y, ff);
        }

        // pass 2: per-channel mix, write result back into own smem slot
        #pragma unroll 8
        for (int c = 0; c < C; c++) {
            ulonglong2 A = m2row[c*2];
            ulonglong2 B = m2row[c*2 + 1];
            unsigned long long acc = 0ull;
            fma2(acc, A.x, mid0);
            fma2(acc, A.y, mid1);
            fma2(acc, B.x, mid2);
            fma2(acc, B.y, mid3);
            float lo, hi;
            asm("mov.b64 {%0, %1}, %2;" : "=f"(lo), "=f"(hi) : "l"(acc));
            s_fea[c*256 + sidx] += lo + hi;
        }
        __syncthreads();

        // pass 3: transposed read (conflict-free via swizzle), coalesced streaming store
        int pw2 = tid & 3;
        int q2  = tid >> 2;
        int ridx = pw2 * 64 + (q2 ^ (pw2 * 8));
        float* op = out + ((size_t)b * C * (HS*WSZ) + (size_t)hh * WSZ + tid);
        #pragma unroll 8
        for (int c = 0; c < C; c++) {
            __stcs(op + (size_t)c * (HS*WSZ), s_fea[c*256 + ridx]);
        }
    } else {
        // general fallback: arbitrary offsets, masked bilinear on original x
        int p = ph * 4 + pw;
        float fea[C];
        float mid[KD];
        for (int k = 0; k < KD; k++) mid[k] = 0.f;
        float* op = out + ((size_t)b * C * (HS*WSZ) + (size_t)hh * WSZ + ww);
        for (int c = 0; c < C; c++) {
            float offx = g_off[c][p][0];
            float offy = g_off[c][p][1];
            float px = (ww + 0.5f) * 0.25f - 0.5f + offx;
            float py = (hh + 0.5f) * 0.25f - 0.5f + offy;
            float fx = floorf(px), fy = floorf(py);
            int x0 = (int)fx, y0 = (int)fy;
            float wx = px - fx, wy = py - fy;
            const float* pl = x + (size_t)(b*C + c) * (H*W);
            float t00 = 0.f, t01 = 0.f, t10 = 0.f, t11 = 0.f;
            if (y0 >= 0 && y0 <= H-1) {
                if (x0 >= 0 && x0 <= W-1)     t00 = pl[y0*W + x0];
                if (x0+1 >= 0 && x0+1 <= W-1) t01 = pl[y0*W + x0 + 1];
            }
            if (y0+1 >= 0 && y0+1 <= H-1) {
                if (x0 >= 0 && x0 <= W-1)     t10 = pl[(y0+1)*W + x0];
                if (x0+1 >= 0 && x0+1 <= W-1) t11 = pl[(y0+1)*W + x0 + 1];
            }
            float f = t00*(1.f-wy)*(1.f-wx) + t01*(1.f-wy)*wx + t10*wy*(1.f-wx) + t11*wy*wx;
            fea[c] = f;
            for (int k = 0; k < KD; k++) mid[k] += s_M1[(pw*C + c)*KD + k] * f;
        }
        for (int c = 0; c < C; c++) {
            float acc = 0.f;
            for (int k = 0; k < KD; k++) acc += s_M2[(pw*C + c)*KD + k] * mid[k];
            op[(size_t)c * (HS*WSZ)] = fea[c] + acc;
        }
    }
}

// ---------------- launch ----------------
extern "C" void kernel_launch(void* const* d_in, const int* in_sizes, int n_in,
                              void* d_out, int out_size) {
    const float* x   = (const float*)d_in[0];
    const float* wcw = (const float*)d_in[1];
    const float* wew = (const float*)d_in[2];
    const float* Wb1 = (const float*)d_in[3];
    const float* bb1 = (const float*)d_in[4];
    const float* Wb2 = (const float*)d_in[5];
    const float* bb2 = (const float*)d_in[6];
    const float* Wr1 = (const float*)d_in[7];
    const float* br1 = (const float*)d_in[8];
    const float* Wr2 = (const float*)d_in[9];
    const float* br2 = (const float*)d_in[10];
    const float* Wq1 = (const float*)d_in[11];
    const float* bq1 = (const float*)d_in[12];
    const float* Wq2 = (const float*)d_in[13];
    const float* bq2 = (const float*)d_in[14];
    const float* Wq3 = (const float*)d_in[15];
    const float* bq3 = (const float*)d_in[16];
    const float* Wo1 = (const float*)d_in[17];
    const float* bo1 = (const float*)d_in[18];
    const float* Wo2 = (const float*)d_in[19];
    const float* bo2 = (const float*)d_in[20];
    const float* Wo3 = (const float*)d_in[21];
    const float* bo3 = (const float*)d_in[22];
    float* out = (float*)d_out;

    const int PRE2_SMEM = 9856 * 4;   // 39424 B
    cudaFuncSetAttribute(k_main, cudaFuncAttributeMaxDynamicSharedMemorySize, 87040);

    k_prep<<<PAD_BLOCKS + 64, 256>>>(x);
    k_pre2<<<80, 256, PRE2_SMEM>>>(Wb1, bb1, Wb2, bb2, Wr1, br1, Wr2, br2,
                                   Wq1, bq1, Wq2, bq2, Wq3, bq3, wcw, wew,
                                   Wo1, bo1, Wo2, bo2, Wo3, bo3);
    k_main<<<BS*HS, 256, 87040>>>(x, out);
}